// round 15
// baseline (speedup 1.0000x reference)
#include <cuda_runtime.h>
#include <cuda_fp16.h>
#include <cstdint>
#include <cstddef>

#define TSTEPS 512
#define BATCH  64
#define DIM    512
#define HID    512
#define GDIM   2048            // 4*HID
#define LSTM_BLOCKS 256        // (4 batch quarters) x (64 j-column blocks)
#define BROWS 16               // batch rows per block
#define JB 8                   // hidden columns per recurrent block
#define HS2 528                // fp16 h_s row stride (conflict-free LDS.64)
#define RED_B 36               // padded partial row stride (fp32)
#define RED_W (BROWS * RED_B)  // one K-group's partial tile
#define NKW 4                  // split-K groups (= warps per block)
#define XKT 64                 // xproj K-tile (fp16)
#define XS 72                  // xproj SMEM row stride in halves (64+8)
#define XGROUPS 256            // xproj m-tile groups (32768/128), 2 timesteps each

// fp16 layout permutation within each 16-col group: puts mma pairs
// (k,k+1),(k+8,k+9) adjacent so the A fragment is one LDS.64.
__host__ __device__ __forceinline__ int pjmap16(int c) {
    int p = (c >> 1) & 7, u = c & 1;
    int off = (p < 4) ? (4 * p) : (4 * (p - 4) + 2);
    return (c & ~15) | (off + u);
}

// ---------------- scratch (static device allocations; no cudaMalloc) -------
__device__ float  g_xproj[(size_t)TSTEPS * BATCH * GDIM];  // x@W_ih^T + bias
__device__ __half g_hbuf[2][BATCH * HID];                  // ping-pong hidden (fp16, PERMUTED)
__device__ unsigned g_cnt2[LSTM_BLOCKS * 8];               // lstm per-block counters
__device__ unsigned g_xcnt[XGROUPS * 8];                   // xproj per-m-tile-group counters

// ---------------- helpers ---------------------------------------------------
__device__ __forceinline__ void mma_f16(float c[4], const uint32_t a[4], const uint32_t b[2]) {
    asm volatile(
        "mma.sync.aligned.m16n8k16.row.col.f32.f16.f16.f32 "
        "{%0,%1,%2,%3}, {%4,%5,%6,%7}, {%8,%9}, {%0,%1,%2,%3};"
        : "+f"(c[0]), "+f"(c[1]), "+f"(c[2]), "+f"(c[3])
        : "r"(a[0]), "r"(a[1]), "r"(a[2]), "r"(a[3]), "r"(b[0]), "r"(b[1]));
}
__device__ __forceinline__ uint32_t packh2(float lo, float hi) {
    __half2 h = __floats2half2_rn(lo, hi);
    uint32_t r; memcpy(&r, &h, 4);
    return r;
}
__device__ __forceinline__ float ex2f(float x) { float y; asm("ex2.approx.f32 %0, %1;" : "=f"(y) : "f"(x)); return y; }
__device__ __forceinline__ float rcpf(float x) { float y; asm("rcp.approx.f32 %0, %1;" : "=f"(y) : "f"(x)); return y; }
__device__ __forceinline__ float sigf(float x)  { return rcpf(1.0f + ex2f(-1.4426950408889634f * x)); }
__device__ __forceinline__ float tanhf_(float x){ return 2.0f * sigf(2.0f * x) - 1.0f; }

__device__ __forceinline__ unsigned ld_acq(const unsigned* p) {
    unsigned v; asm volatile("ld.acquire.gpu.global.u32 %0, [%1];" : "=r"(v) : "l"(p)); return v;
}
__device__ __forceinline__ void arrive_release(unsigned* p) {
    asm volatile("red.release.gpu.global.add.u32 [%0], 1;" :: "l"(p) : "memory");
}
__device__ __forceinline__ void cp16(uint32_t s, const void* g) {
    asm volatile("cp.async.cg.shared.global [%0], [%1], 16;" :: "r"(s), "l"(g));
}

// ============================================================================
// Kernel 0: reset all sync counters (must precede BOTH kernels).
// ============================================================================
__global__ void reset_kernel() {
    for (int i = threadIdx.x; i < LSTM_BLOCKS * 8; i += 256) g_cnt2[i] = 0u;
    for (int i = threadIdx.x; i < XGROUPS * 8;     i += 256) g_xcnt[i] = 0u;
}

// ============================================================================
// Kernel 1: x_proj = X @ W_ih^T + bias — fp16 mma.m16n8k16, fp32 accumulate.
// Runs CONCURRENTLY with the lstm kernel (forked stream). After each block's
// tile is stored, it release-arrives on g_xcnt[m-tile group]; a group is
// complete (covers 2 timesteps) at 16 arrivals.
// ============================================================================
__global__ void __launch_bounds__(256) xproj_kernel(
    const float* __restrict__ X, const float* __restrict__ Wih,
    const float* __restrict__ b_ih, const float* __restrict__ b_hh)
{
    __shared__ __half As[128][XS];
    __shared__ __half Bs[128][XS];

    const int m0 = blockIdx.y * 128;
    const int n0 = blockIdx.x * 128;
    const int tid  = threadIdx.x;
    const int lane = tid & 31;
    const int warp = tid >> 5;
    const int wm = warp >> 1;       // 0..3 : 32 output rows each
    const int wn = warp & 1;        // 0..1 : 64 output cols each
    const int gid = lane >> 2;      // 0..7
    const int tig = lane & 3;       // 0..3

    float acc[2][8][4];
    #pragma unroll
    for (int mt = 0; mt < 2; mt++)
        #pragma unroll
        for (int nt = 0; nt < 8; nt++)
            #pragma unroll
            for (int q = 0; q < 4; q++) acc[mt][nt][q] = 0.0f;

    for (int kt = 0; kt < DIM / XKT; kt++) {
        __syncthreads();
        #pragma unroll
        for (int it = 0; it < 8; it++) {
            int e  = it * 256 + tid;
            int r  = e >> 4;
            int c4 = (e & 15) * 4;
            float4 va = *(const float4*)(X + (size_t)(m0 + r) * DIM + kt * XKT + c4);
            *(uint32_t*)&As[r][c4]     = packh2(va.x, va.y);
            *(uint32_t*)&As[r][c4 + 2] = packh2(va.z, va.w);
            float4 vb = *(const float4*)(Wih + (size_t)(n0 + r) * DIM + kt * XKT + c4);
            *(uint32_t*)&Bs[r][c4]     = packh2(vb.x, vb.y);
            *(uint32_t*)&Bs[r][c4 + 2] = packh2(vb.z, vb.w);
        }
        __syncthreads();

        #pragma unroll
        for (int ks = 0; ks < 4; ks++) {
            const int kb = ks * 16;
            uint32_t a[2][4], b[8][2];
            #pragma unroll
            for (int mt = 0; mt < 2; mt++) {
                int row = wm * 32 + mt * 16 + gid;
                a[mt][0] = *(const uint32_t*)&As[row    ][kb + 2 * tig];
                a[mt][1] = *(const uint32_t*)&As[row + 8][kb + 2 * tig];
                a[mt][2] = *(const uint32_t*)&As[row    ][kb + 2 * tig + 8];
                a[mt][3] = *(const uint32_t*)&As[row + 8][kb + 2 * tig + 8];
            }
            #pragma unroll
            for (int nt = 0; nt < 8; nt++) {
                int col = wn * 64 + nt * 8 + gid;
                b[nt][0] = *(const uint32_t*)&Bs[col][kb + 2 * tig];
                b[nt][1] = *(const uint32_t*)&Bs[col][kb + 2 * tig + 8];
            }
            #pragma unroll
            for (int mt = 0; mt < 2; mt++)
                #pragma unroll
                for (int nt = 0; nt < 8; nt++)
                    mma_f16(acc[mt][nt], a[mt], b[nt]);
        }
    }

    // epilogue: add bias, write fp32
    #pragma unroll
    for (int mt = 0; mt < 2; mt++) {
        #pragma unroll
        for (int nt = 0; nt < 8; nt++) {
            int row = m0 + wm * 32 + mt * 16 + gid;
            int col = n0 + wn * 64 + nt * 8 + 2 * tig;
            float bz0 = b_ih[col]     + b_hh[col];
            float bz1 = b_ih[col + 1] + b_hh[col + 1];
            float2 v0 = make_float2(acc[mt][nt][0] + bz0, acc[mt][nt][1] + bz1);
            float2 v1 = make_float2(acc[mt][nt][2] + bz0, acc[mt][nt][3] + bz1);
            *(float2*)(g_xproj + (size_t)row       * GDIM + col) = v0;
            *(float2*)(g_xproj + (size_t)(row + 8) * GDIM + col) = v1;
        }
    }

    // publish: this block's tile of m-group blockIdx.y is done
    __syncthreads();
    if (tid == 0) {
        __threadfence();
        arrive_release(&g_xcnt[blockIdx.y * 8]);
    }
}

// ============================================================================
// Kernel 2: persistent recurrence (R14 structure) + x_proj readiness polls
// in the shadow phase (overlapped producer).
// ============================================================================
__global__ void __launch_bounds__(128, 2) lstm_kernel(
    const float* __restrict__ mask, const float* __restrict__ h0,
    const float* __restrict__ Whh, float* __restrict__ out)
{
    extern __shared__ char smem_raw[];
    __half* h_s  = (__half*)smem_raw;                        // 16 x 528 fp16
    float*  red  = (float*)(smem_raw + BROWS * HS2 * 2);     // 4 x 16 x 36 fp32
    float*  h0_s = red + NKW * RED_W;                        // 128
    float*  c_s  = h0_s + 128;                               // 128

    const int tid  = threadIdx.x;
    const int blk  = blockIdx.x;
    const int bb   = blk >> 6;                // batch quarter 0..3
    const int jb   = blk & 63;                // j-block 0..63
    const int j0   = jb * JB;
    const int b0   = bb * BROWS;
    const int lane = tid & 31;
    const int kw   = tid >> 5;                // warp = K-group 0..3
    const int gid  = lane >> 2;
    const int tig  = lane & 3;
    const int kbase = kw * 128;

    // --- W_hh fragments straight from gmem (init-only), fp16-packed.
    uint32_t breg[8][4][2];
    #pragma unroll
    for (int kk = 0; kk < 8; kk++)
        #pragma unroll
        for (int nt = 0; nt < 4; nt++) {
            const float* wr = Whh + (size_t)(nt * HID + j0 + gid) * HID
                            + kbase + kk * 16 + 2 * tig;
            breg[kk][nt][0] = packh2(wr[0], wr[1]);
            breg[kk][nt][1] = packh2(wr[8], wr[9]);
        }

    // --- h0 slice (16 rows x 8 cols), c0 = h0; publish permuted fp16 h0
    for (int i = tid; i < BROWS * JB; i += 128) {
        int b = i >> 3, jl = i & 7;
        float v = h0[(b0 + b) * HID + j0 + jl];
        h0_s[i] = v;
        c_s[i]  = v;
        g_hbuf[0][(b0 + b) * HID + pjmap16(j0 + jl)] = __float2half_rn(v);
    }
    __syncthreads();
    if (lane == 0) arrive_release(&g_cnt2[blk * 8]);

    const int rb = tid >> 3;           // 0..15 local batch row for reduce
    const int jl = tid & 7;            // 0..7 local hidden col

    const uint32_t hss = (uint32_t)__cvta_generic_to_shared(h_s);
    const unsigned* pollp = &g_cnt2[(bb * 64 + kw * 16 + (lane & 15)) * 8];

    // wait for x_proj group 0 (timesteps 0-1) then prefetch t=0
    while (ld_acq(&g_xcnt[0]) < 16u) { }
    float xq[4];
    {
        const float* xp = g_xproj + (size_t)(b0 + rb) * GDIM + j0 + jl;
        #pragma unroll
        for (int g = 0; g < 4; g++) xq[g] = xp[g * HID];
    }
    float mval = mask[b0 + rb];

    const int jperm = pjmap16(j0 + jl);

    for (int t = 0; t < TSTEPS; t++) {
        const __half* hin  = g_hbuf[t & 1];
        __half*       hout = g_hbuf[(t + 1) & 1];

        {
            const unsigned want = 4u * (unsigned)(t + 1);
            for (;;) {
                unsigned cv = ld_acq(pollp);
                if (__all_sync(0xffffffffu, cv >= want)) break;
            }
        }

        #pragma unroll
        for (int g = 0; g < 2; g++) {
            #pragma unroll 4
            for (int it = 0; it < 4; it++) {
                int e   = it * 32 + lane;
                int row = e >> 3;
                int ce  = g * 64 + (e & 7) * 8;
                cp16(hss + (uint32_t)(row * HS2 + kbase + ce) * 2,
                     hin + (size_t)(b0 + row) * HID + kbase + ce);
            }
            asm volatile("cp.async.commit_group;" ::: "memory");
        }

        float acc[4][4];
        #pragma unroll
        for (int nt = 0; nt < 4; nt++)
            #pragma unroll
            for (int q = 0; q < 4; q++) acc[nt][q] = 0.0f;

#define DO_HALF(K0, PEND)                                                       \
        {                                                                       \
            asm volatile("cp.async.wait_group " #PEND ";" ::: "memory");        \
            __syncwarp();                                                       \
            _Pragma("unroll")                                                   \
            for (int kk = (K0); kk < (K0) + 4; kk++) {                          \
                uint2 v0 = *(const uint2*)&h_s[gid * HS2                        \
                                  + kbase + kk * 16 + 4 * tig];                 \
                uint2 v1 = *(const uint2*)&h_s[(gid + 8) * HS2                  \
                                  + kbase + kk * 16 + 4 * tig];                 \
                uint32_t a[4];                                                  \
                a[0] = v0.x;                                                    \
                a[1] = v1.x;                                                    \
                a[2] = v0.y;                                                    \
                a[3] = v1.y;                                                    \
                _Pragma("unroll")                                               \
                for (int nt = 0; nt < 4; nt++)                                  \
                    mma_f16(acc[nt], a, breg[kk][nt]);                          \
            }                                                                   \
        }
        DO_HALF(0, 1)
        DO_HALF(4, 0)
#undef DO_HALF

        float* rw = red + kw * RED_W;
        #pragma unroll
        for (int nt = 0; nt < 4; nt++) {
            int col = nt * 8 + 2 * tig;
            float* rp = &rw[gid * RED_B + col];
            *(float2*)rp               = make_float2(acc[nt][0], acc[nt][1]);
            *(float2*)(rp + 8 * RED_B) = make_float2(acc[nt][2], acc[nt][3]);
        }
        __syncthreads();                       // bar A

        float s[4];
        #pragma unroll
        for (int g = 0; g < 4; g++) s[g] = xq[g];
        #pragma unroll
        for (int w = 0; w < NKW; w++) {
            const float* rr = red + w * RED_W + rb * RED_B + jl;
            #pragma unroll
            for (int g = 0; g < 4; g++) s[g] += rr[g * 8];
        }
        float iv = sigf(s[0]);
        float fv = sigf(s[1]);
        float gv = tanhf_(s[2]);
        float ov = sigf(s[3]);
        int p = rb * 8 + jl;
        float c = fv * c_s[p] + iv * gv;
        float h = ov * tanhf_(c);
        float z = h0_s[p];                     // h0 == c0
        h = h * mval + z * (1.0f - mval);
        c = c * mval + z * (1.0f - mval);
        c_s[p] = c;
        hout[(size_t)(b0 + rb) * HID + jperm] = __float2half_rn(h);
        __syncwarp();
        if (lane == 0) arrive_release(&g_cnt2[blk * 8]);

        // ---- shadow: out[] stores + next-step prefetch (xproj-gated)
        {
            int grow = b0 + rb, gcol = j0 + jl;
            out[(size_t)t * BATCH * HID + grow * HID + gcol] = h;
            if (t == TSTEPS - 1) {
                out[(size_t)TSTEPS * BATCH * HID               + grow * HID + gcol] = h;
                out[(size_t)TSTEPS * BATCH * HID + BATCH * HID + grow * HID + gcol] = c;
            }
        }
        if (t + 1 < TSTEPS) {
            // wait for x_proj group covering timestep t+1 (2 steps per group)
            const unsigned* xc = &g_xcnt[((t + 1) >> 1) * 8];
            while (ld_acq(xc) < 16u) { }
            const float* xp = g_xproj + (size_t)(t + 1) * BATCH * GDIM
                            + (size_t)(b0 + rb) * GDIM + j0 + jl;
            #pragma unroll
            for (int g = 0; g < 4; g++) xq[g] = xp[g * HID];
            mval = mask[(t + 1) * BATCH + b0 + rb];
        }
        __syncthreads();                       // bar B
    }
}

// ============================================================================
extern "C" void kernel_launch(void* const* d_in, const int* in_sizes, int n_in,
                              void* d_out, int out_size) {
    const float* inputs = (const float*)d_in[0];   // [512,64,512]
    const float* mask   = (const float*)d_in[1];   // [512,64]
    const float* h0     = (const float*)d_in[2];   // [64,512]
    const float* W_ih   = (const float*)d_in[3];   // [2048,512]
    const float* W_hh   = (const float*)d_in[4];   // [2048,512]
    const float* b_ih   = (const float*)d_in[5];   // [2048]
    const float* b_hh   = (const float*)d_in[6];   // [2048]
    float* out = (float*)d_out;                    // out | hT | cT (fp32)

    const int smem_bytes = BROWS * HS2 * 2 + (NKW * RED_W + 256 + 32) * 4;
    cudaFuncSetAttribute(lstm_kernel, cudaFuncAttributeMaxDynamicSharedMemorySize, smem_bytes);

    // fork a side stream so xproj overlaps the recurrence (graph-capturable:
    // stream/event creation is not a captured op; the fork/join edges are).
    cudaStream_t s1;
    cudaStreamCreateWithFlags(&s1, cudaStreamNonBlocking);
    cudaEvent_t ev_fork, ev_join;
    cudaEventCreateWithFlags(&ev_fork, cudaEventDisableTiming);
    cudaEventCreateWithFlags(&ev_join, cudaEventDisableTiming);

    reset_kernel<<<1, 256>>>();                    // stream 0: counters first

    cudaEventRecord(ev_fork, 0);
    cudaStreamWaitEvent(s1, ev_fork, 0);

    dim3 xg(GDIM / 128, (TSTEPS * BATCH) / 128);   // (16, 256)
    xproj_kernel<<<xg, 256, 0, s1>>>(inputs, W_ih, b_ih, b_hh);
    cudaEventRecord(ev_join, s1);

    lstm_kernel<<<LSTM_BLOCKS, 128, smem_bytes>>>(mask, h0, W_hh, out);

    cudaStreamWaitEvent(0, ev_join, 0);            // join side branch
}

// round 17
// speedup vs baseline: 1.0189x; 1.0189x over previous
#include <cuda_runtime.h>
#include <cuda_fp16.h>
#include <cstdint>
#include <cstddef>

#define TSTEPS 512
#define BATCH  64
#define DIM    512
#define HID    512
#define GDIM   2048            // 4*HID
#define LSTM_BLOCKS 256        // (4 batch quarters) x (64 j-column blocks)
#define BROWS 16               // batch rows per block
#define JB 8                   // hidden columns per recurrent block
#define HS2 528                // fp16 h_s row stride (conflict-free LDS.64)
#define RED_B 36               // padded partial row stride (fp32)
#define RED_W (BROWS * RED_B)  // one K-group's partial tile
#define RED_P (NKW * RED_W)    // one parity's partial buffer
#define NKW 4                  // split-K groups (= warps per block)
#define XKT 64                 // xproj K-tile (fp16)
#define XS 72                  // xproj SMEM row stride in halves (64+8)

// fp16 layout permutation within each 16-col group: puts mma pairs
// (k,k+1),(k+8,k+9) adjacent so the A fragment is one LDS.64.
__host__ __device__ __forceinline__ int pjmap16(int c) {
    int p = (c >> 1) & 7, u = c & 1;
    int off = (p < 4) ? (4 * p) : (4 * (p - 4) + 2);
    return (c & ~15) | (off + u);
}

// ---------------- scratch (static device allocations; no cudaMalloc) -------
__device__ float  g_xproj[(size_t)TSTEPS * BATCH * GDIM];  // x@W_ih^T + bias
__device__ __half g_hbuf[2][BATCH * HID];                  // ping-pong hidden (fp16, PERMUTED)
__device__ unsigned g_cnt2[LSTM_BLOCKS * 8];               // lstm per-block counters

// ---------------- helpers ---------------------------------------------------
__device__ __forceinline__ void mma_f16(float c[4], const uint32_t a[4], const uint32_t b[2]) {
    asm volatile(
        "mma.sync.aligned.m16n8k16.row.col.f32.f16.f16.f32 "
        "{%0,%1,%2,%3}, {%4,%5,%6,%7}, {%8,%9}, {%0,%1,%2,%3};"
        : "+f"(c[0]), "+f"(c[1]), "+f"(c[2]), "+f"(c[3])
        : "r"(a[0]), "r"(a[1]), "r"(a[2]), "r"(a[3]), "r"(b[0]), "r"(b[1]));
}
__device__ __forceinline__ uint32_t packh2(float lo, float hi) {
    __half2 h = __floats2half2_rn(lo, hi);
    uint32_t r; memcpy(&r, &h, 4);
    return r;
}
__device__ __forceinline__ float ex2f(float x) { float y; asm("ex2.approx.f32 %0, %1;" : "=f"(y) : "f"(x)); return y; }
__device__ __forceinline__ float rcpf(float x) { float y; asm("rcp.approx.f32 %0, %1;" : "=f"(y) : "f"(x)); return y; }
__device__ __forceinline__ float sigf(float x)  { return rcpf(1.0f + ex2f(-1.4426950408889634f * x)); }
__device__ __forceinline__ float tanhf_(float x){ return 2.0f * sigf(2.0f * x) - 1.0f; }

__device__ __forceinline__ unsigned ld_acq(const unsigned* p) {
    unsigned v; asm volatile("ld.acquire.gpu.global.u32 %0, [%1];" : "=r"(v) : "l"(p)); return v;
}
__device__ __forceinline__ void arrive_release(unsigned* p) {
    asm volatile("red.release.gpu.global.add.u32 [%0], 1;" :: "l"(p) : "memory");
}
__device__ __forceinline__ void cp16(uint32_t s, const void* g) {
    asm volatile("cp.async.cg.shared.global [%0], [%1], 16;" :: "r"(s), "l"(g));
}

// ============================================================================
// Kernel 1: x_proj = X @ W_ih^T + bias — fp16 mma.m16n8k16, fp32 accumulate.
// M = 32768, N = 2048, K = 512, 128x128 tiles, K-tile 64 (8 iterations).
// __launch_bounds__(256, 2) caps regs at 128 so TWO blocks co-reside per SM:
// one block's MMA phase hides the other's tile-load latency.
// Also resets the lstm counters.
// ============================================================================
__global__ void __launch_bounds__(256, 2) xproj_kernel(
    const float* __restrict__ X, const float* __restrict__ Wih,
    const float* __restrict__ b_ih, const float* __restrict__ b_hh)
{
    {
        int bid = blockIdx.y * gridDim.x + blockIdx.x;
        if (threadIdx.x == 0 && bid < LSTM_BLOCKS * 8) g_cnt2[bid] = 0u;
    }

    __shared__ __half As[128][XS];
    __shared__ __half Bs[128][XS];

    const int m0 = blockIdx.y * 128;
    const int n0 = blockIdx.x * 128;
    const int tid  = threadIdx.x;
    const int lane = tid & 31;
    const int warp = tid >> 5;
    const int wm = warp >> 1;       // 0..3 : 32 output rows each
    const int wn = warp & 1;        // 0..1 : 64 output cols each
    const int gid = lane >> 2;      // 0..7
    const int tig = lane & 3;       // 0..3

    float acc[2][8][4];
    #pragma unroll
    for (int mt = 0; mt < 2; mt++)
        #pragma unroll
        for (int nt = 0; nt < 8; nt++)
            #pragma unroll
            for (int q = 0; q < 4; q++) acc[mt][nt][q] = 0.0f;

    for (int kt = 0; kt < DIM / XKT; kt++) {
        __syncthreads();
        // load + convert tile: 128 rows x 64 cols fp32 -> fp16 (A and B)
        #pragma unroll
        for (int it = 0; it < 8; it++) {
            int e  = it * 256 + tid;
            int r  = e >> 4;
            int c4 = (e & 15) * 4;
            float4 va = *(const float4*)(X + (size_t)(m0 + r) * DIM + kt * XKT + c4);
            *(uint32_t*)&As[r][c4]     = packh2(va.x, va.y);
            *(uint32_t*)&As[r][c4 + 2] = packh2(va.z, va.w);
            float4 vb = *(const float4*)(Wih + (size_t)(n0 + r) * DIM + kt * XKT + c4);
            *(uint32_t*)&Bs[r][c4]     = packh2(vb.x, vb.y);
            *(uint32_t*)&Bs[r][c4 + 2] = packh2(vb.z, vb.w);
        }
        __syncthreads();

        #pragma unroll
        for (int ks = 0; ks < 4; ks++) {
            const int kb = ks * 16;
            uint32_t a[2][4], b[8][2];
            #pragma unroll
            for (int mt = 0; mt < 2; mt++) {
                int row = wm * 32 + mt * 16 + gid;
                a[mt][0] = *(const uint32_t*)&As[row    ][kb + 2 * tig];
                a[mt][1] = *(const uint32_t*)&As[row + 8][kb + 2 * tig];
                a[mt][2] = *(const uint32_t*)&As[row    ][kb + 2 * tig + 8];
                a[mt][3] = *(const uint32_t*)&As[row + 8][kb + 2 * tig + 8];
            }
            #pragma unroll
            for (int nt = 0; nt < 8; nt++) {
                int col = wn * 64 + nt * 8 + gid;
                b[nt][0] = *(const uint32_t*)&Bs[col][kb + 2 * tig];
                b[nt][1] = *(const uint32_t*)&Bs[col][kb + 2 * tig + 8];
            }
            #pragma unroll
            for (int mt = 0; mt < 2; mt++)
                #pragma unroll
                for (int nt = 0; nt < 8; nt++)
                    mma_f16(acc[mt][nt], a[mt], b[nt]);
        }
    }

    // epilogue: add bias, write fp32
    #pragma unroll
    for (int mt = 0; mt < 2; mt++) {
        #pragma unroll
        for (int nt = 0; nt < 8; nt++) {
            int row = m0 + wm * 32 + mt * 16 + gid;
            int col = n0 + wn * 64 + nt * 8 + 2 * tig;
            float bz0 = b_ih[col]     + b_hh[col];
            float bz1 = b_ih[col + 1] + b_hh[col + 1];
            float2 v0 = make_float2(acc[mt][nt][0] + bz0, acc[mt][nt][1] + bz1);
            float2 v1 = make_float2(acc[mt][nt][2] + bz0, acc[mt][nt][3] + bz1);
            *(float2*)(g_xproj + (size_t)row       * GDIM + col) = v0;
            *(float2*)(g_xproj + (size_t)(row + 8) * GDIM + col) = v1;
        }
    }
}

// ============================================================================
// Kernel 2: persistent recurrence (R14 structure) with DOUBLE-BUFFERED
// partials -> single __syncthreads per step (bar B removed).
// 256 blocks = (4 quarters) x (64 j-blocks); 128 threads (4 warps = split-K).
// Safety of bar-B removal: red[parity] reads (step t) complete before
// bar A(t+1); next same-parity writes (step t+2) occur after bar A(t+1).
// h_s / c_s / xq are warp- or thread-private.
// ============================================================================
__global__ void __launch_bounds__(128, 2) lstm_kernel(
    const float* __restrict__ mask, const float* __restrict__ h0,
    const float* __restrict__ Whh, float* __restrict__ out)
{
    extern __shared__ char smem_raw[];
    __half* h_s  = (__half*)smem_raw;                        // 16 x 528 fp16
    float*  red  = (float*)(smem_raw + BROWS * HS2 * 2);     // 2 x 4 x 16 x 36 fp32
    float*  h0_s = red + 2 * RED_P;                          // 128
    float*  c_s  = h0_s + 128;                               // 128

    const int tid  = threadIdx.x;
    const int blk  = blockIdx.x;
    const int bb   = blk >> 6;                // batch quarter 0..3
    const int jb   = blk & 63;                // j-block 0..63
    const int j0   = jb * JB;
    const int b0   = bb * BROWS;
    const int lane = tid & 31;
    const int kw   = tid >> 5;                // warp = K-group 0..3
    const int gid  = lane >> 2;
    const int tig  = lane & 3;
    const int kbase = kw * 128;

    // --- W_hh fragments straight from gmem (init-only), fp16-packed.
    uint32_t breg[8][4][2];
    #pragma unroll
    for (int kk = 0; kk < 8; kk++)
        #pragma unroll
        for (int nt = 0; nt < 4; nt++) {
            const float* wr = Whh + (size_t)(nt * HID + j0 + gid) * HID
                            + kbase + kk * 16 + 2 * tig;
            breg[kk][nt][0] = packh2(wr[0], wr[1]);
            breg[kk][nt][1] = packh2(wr[8], wr[9]);
        }

    // --- h0 slice (16 rows x 8 cols), c0 = h0; publish permuted fp16 h0
    for (int i = tid; i < BROWS * JB; i += 128) {
        int b = i >> 3, jl = i & 7;
        float v = h0[(b0 + b) * HID + j0 + jl];
        h0_s[i] = v;
        c_s[i]  = v;
        g_hbuf[0][(b0 + b) * HID + pjmap16(j0 + jl)] = __float2half_rn(v);
    }
    __syncthreads();
    if (lane == 0) arrive_release(&g_cnt2[blk * 8]);

    const int rb = tid >> 3;           // 0..15 local batch row for reduce
    const int jl = tid & 7;            // 0..7 local hidden col

    const uint32_t hss = (uint32_t)__cvta_generic_to_shared(h_s);
    const unsigned* pollp = &g_cnt2[(bb * 64 + kw * 16 + (lane & 15)) * 8];

    float xq[4];
    {
        const float* xp = g_xproj + (size_t)(b0 + rb) * GDIM + j0 + jl;
        #pragma unroll
        for (int g = 0; g < 4; g++) xq[g] = xp[g * HID];
    }
    float mval = mask[b0 + rb];

    const int jperm = pjmap16(j0 + jl);

    for (int t = 0; t < TSTEPS; t++) {
        const __half* hin  = g_hbuf[t & 1];
        __half*       hout = g_hbuf[(t + 1) & 1];

        {
            const unsigned want = 4u * (unsigned)(t + 1);
            for (;;) {
                unsigned cv = ld_acq(pollp);
                if (__all_sync(0xffffffffu, cv >= want)) break;
            }
        }

        #pragma unroll
        for (int g = 0; g < 2; g++) {
            #pragma unroll 4
            for (int it = 0; it < 4; it++) {
                int e   = it * 32 + lane;
                int row = e >> 3;
                int ce  = g * 64 + (e & 7) * 8;
                cp16(hss + (uint32_t)(row * HS2 + kbase + ce) * 2,
                     hin + (size_t)(b0 + row) * HID + kbase + ce);
            }
            asm volatile("cp.async.commit_group;" ::: "memory");
        }

        float acc[4][4];
        #pragma unroll
        for (int nt = 0; nt < 4; nt++)
            #pragma unroll
            for (int q = 0; q < 4; q++) acc[nt][q] = 0.0f;

#define DO_HALF(K0, PEND)                                                       \
        {                                                                       \
            asm volatile("cp.async.wait_group " #PEND ";" ::: "memory");        \
            __syncwarp();                                                       \
            _Pragma("unroll")                                                   \
            for (int kk = (K0); kk < (K0) + 4; kk++) {                          \
                uint2 v0 = *(const uint2*)&h_s[gid * HS2                        \
                                  + kbase + kk * 16 + 4 * tig];                 \
                uint2 v1 = *(const uint2*)&h_s[(gid + 8) * HS2                  \
                                  + kbase + kk * 16 + 4 * tig];                 \
                uint32_t a[4];                                                  \
                a[0] = v0.x;                                                    \
                a[1] = v1.x;                                                    \
                a[2] = v0.y;                                                    \
                a[3] = v1.y;                                                    \
                _Pragma("unroll")                                               \
                for (int nt = 0; nt < 4; nt++)                                  \
                    mma_f16(acc[nt], a, breg[kk][nt]);                          \
            }                                                                   \
        }
        DO_HALF(0, 1)
        DO_HALF(4, 0)
#undef DO_HALF

        // ---- store partials: red[parity][kw][row][col]
        float* rw = red + (t & 1) * RED_P + kw * RED_W;
        #pragma unroll
        for (int nt = 0; nt < 4; nt++) {
            int col = nt * 8 + 2 * tig;
            float* rp = &rw[gid * RED_B + col];
            *(float2*)rp               = make_float2(acc[nt][0], acc[nt][1]);
            *(float2*)(rp + 8 * RED_B) = make_float2(acc[nt][2], acc[nt][3]);
        }
        __syncthreads();                       // bar A (only barrier per step)

        // ---- reduce 4 partials + x_proj, LSTM cell (1 value per thread)
        const float* rbase = red + (t & 1) * RED_P + rb * RED_B + jl;
        float s[4];
        #pragma unroll
        for (int g = 0; g < 4; g++) s[g] = xq[g];
        #pragma unroll
        for (int w = 0; w < NKW; w++) {
            const float* rr = rbase + w * RED_W;
            #pragma unroll
            for (int g = 0; g < 4; g++) s[g] += rr[g * 8];
        }
        float iv = sigf(s[0]);
        float fv = sigf(s[1]);
        float gv = tanhf_(s[2]);
        float ov = sigf(s[3]);
        int p = rb * 8 + jl;
        float c = fv * c_s[p] + iv * gv;
        float h = ov * tanhf_(c);
        float z = h0_s[p];                     // h0 == c0
        h = h * mval + z * (1.0f - mval);
        c = c * mval + z * (1.0f - mval);
        c_s[p] = c;
        hout[(size_t)(b0 + rb) * HID + jperm] = __float2half_rn(h);
        __syncwarp();
        if (lane == 0) arrive_release(&g_cnt2[blk * 8]);

        // ---- shadow: out[] stores + next-step prefetch (off critical path)
        {
            int grow = b0 + rb, gcol = j0 + jl;
            out[(size_t)t * BATCH * HID + grow * HID + gcol] = h;
            if (t == TSTEPS - 1) {
                out[(size_t)TSTEPS * BATCH * HID               + grow * HID + gcol] = h;
                out[(size_t)TSTEPS * BATCH * HID + BATCH * HID + grow * HID + gcol] = c;
            }
        }
        if (t + 1 < TSTEPS) {
            const float* xp = g_xproj + (size_t)(t + 1) * BATCH * GDIM
                            + (size_t)(b0 + rb) * GDIM + j0 + jl;
            #pragma unroll
            for (int g = 0; g < 4; g++) xq[g] = xp[g * HID];
            mval = mask[(t + 1) * BATCH + b0 + rb];
        }
        // no bar B: red is double-buffered by parity.
    }
}

// ============================================================================
extern "C" void kernel_launch(void* const* d_in, const int* in_sizes, int n_in,
                              void* d_out, int out_size) {
    const float* inputs = (const float*)d_in[0];   // [512,64,512]
    const float* mask   = (const float*)d_in[1];   // [512,64]
    const float* h0     = (const float*)d_in[2];   // [64,512]
    const float* W_ih   = (const float*)d_in[3];   // [2048,512]
    const float* W_hh   = (const float*)d_in[4];   // [2048,512]
    const float* b_ih   = (const float*)d_in[5];   // [2048]
    const float* b_hh   = (const float*)d_in[6];   // [2048]
    float* out = (float*)d_out;                    // out | hT | cT (fp32)

    const int smem_bytes = BROWS * HS2 * 2 + (2 * RED_P + 256 + 32) * 4;
    cudaFuncSetAttribute(lstm_kernel, cudaFuncAttributeMaxDynamicSharedMemorySize, smem_bytes);

    dim3 xg(GDIM / 128, (TSTEPS * BATCH) / 128);   // (16, 256)
    xproj_kernel<<<xg, 256>>>(inputs, W_ih, b_ih, b_hh);

    lstm_kernel<<<LSTM_BLOCKS, 128, smem_bytes>>>(mask, h0, W_hh, out);
}